// round 15
// baseline (speedup 1.0000x reference)
#include <cuda_runtime.h>
#include <cuda_fp16.h>
#include <cstdint>

// ---------------- problem constants ----------------
#define B_ROWS 16384
#define D_FEAT 256
#define H_HID  64
#define O_OUT  256

// ---------------- device scratch (static, allocation-free) ----------------
__device__ __half  g_u[(size_t)B_ROWS * D_FEAT];     // 8.4 MB fp16 u
__device__ __half  g_wc[(size_t)O_OUT * D_FEAT];     // Wc fp16
// transposed tables: [dgroup][idx][dd]  (dd = d & 31, dgroup = d >> 5)
__device__ float   g_knot_t[8 * 64 * 32];
__device__ float2  g_tab_t[8 * 65 * 32];             // (slope, intercept)

__device__ __forceinline__ uint32_t smem_u32(const void* p) {
    uint32_t a;
    asm("{ .reg .u64 t; cvta.to.shared.u64 t, %1; cvt.u32.u64 %0, t; }"
        : "=r"(a) : "l"(p));
    return a;
}

// PDL primitives (sm_90 baseline; OK through the compute_103 PTX stage)
#define PDL_WAIT()    asm volatile("griddepcontrol.wait;" ::: "memory")
#define PDL_TRIGGER() asm volatile("griddepcontrol.launch_dependents;" ::: "memory")

// =====================================================================
// Kernel 1: PWL table build (blocks 0..63, transposed output layout)
//           + Wc fp16 convert (blocks 64..191).
// =====================================================================
__global__ __launch_bounds__(128)
void prep_kernel(const float* __restrict__ W1,
                 const float* __restrict__ b1,
                 const float* __restrict__ W2,
                 const float* __restrict__ b2,
                 const float* __restrict__ Wc)
{
    const int bid = blockIdx.x;

    if (bid >= 64) {
        const float4* W4 = reinterpret_cast<const float4*>(Wc);
        int idx = (bid - 64) * 128 + threadIdx.x;
        float4 f = W4[idx];
        __half2 h0 = __float22half2_rn(make_float2(f.x, f.y));
        __half2 h1 = __float22half2_rn(make_float2(f.z, f.w));
        uint2 pk;
        pk.x = *reinterpret_cast<uint32_t*>(&h0);
        pk.y = *reinterpret_cast<uint32_t*>(&h1);
        *reinterpret_cast<uint2*>(&g_wc[idx * 4]) = pk;
        PDL_TRIGGER();
        return;
    }

    const int w    = threadIdx.x >> 5;
    const int lane = threadIdx.x & 31;
    const int d    = bid * 4 + w;
    const int dg   = d >> 5;            // dgroup 0..7
    const int dd   = d & 31;
    const int kbase = dg * 64 * 32;     // g_knot_t base
    const int tbase = dg * 65 * 32;     // g_tab_t base

    __shared__ float s_t[4][64], s_ds[4][64], s_di[4][64];
    __shared__ float s_kt[4][64], s_kds[4][64], s_kdi[4][64];

    float t[2], ds[2], di[2];
    float bs = 0.0f, bi = 0.0f;
    #pragma unroll
    for (int i = 0; i < 2; i++) {
        const int h  = lane + i * 32;
        const float w1 = W1[d * H_HID + h];
        const float bb = b1[d * H_HID + h];
        const float w2 = W2[d * H_HID + h];
        if (w1 != 0.0f) {
            t[i]  = -bb / w1;
            ds[i] = fabsf(w1) * w2;
            di[i] = (w1 > 0.0f) ? (w2 * bb) : (-w2 * bb);
            if (w1 < 0.0f) { bs += w1 * w2; bi += w2 * bb; }
        } else {
            t[i]  = __int_as_float(0x7f800000);
            ds[i] = 0.0f;
            di[i] = 0.0f;
            bi   += w2 * fmaxf(bb, 0.0f);
        }
        s_t[w][h]  = t[i];
        s_ds[w][h] = ds[i];
        s_di[w][h] = di[i];
    }
    #pragma unroll
    for (int off = 16; off >= 1; off >>= 1) {
        bs += __shfl_xor_sync(0xffffffffu, bs, off);
        bi += __shfl_xor_sync(0xffffffffu, bi, off);
    }
    bi += b2[d];

    __syncwarp();
    int r0 = 0, r1 = 0;
    const float t0 = t[0], t1 = t[1];
    #pragma unroll 16
    for (int j = 0; j < 64; j++) {
        float tj = s_t[w][j];
        r0 += (tj < t0) || (tj == t0 && j < lane);
        r1 += (tj < t1) || (tj == t1 && j < lane + 32);
    }
    s_kt[w][r0]  = t0;  s_kds[w][r0] = ds[0]; s_kdi[w][r0] = di[0];
    s_kt[w][r1]  = t1;  s_kds[w][r1] = ds[1]; s_kdi[w][r1] = di[1];
    __syncwarp();

    const float v0s = s_kds[w][2 * lane],     v1s = s_kds[w][2 * lane + 1];
    const float v0i = s_kdi[w][2 * lane],     v1i = s_kdi[w][2 * lane + 1];
    float incs = v0s + v1s, inci = v0i + v1i;
    const float ps = incs, pi = inci;
    #pragma unroll
    for (int off = 1; off < 32; off <<= 1) {
        float as_ = __shfl_up_sync(0xffffffffu, incs, off);
        float ai_ = __shfl_up_sync(0xffffffffu, inci, off);
        if (lane >= off) { incs += as_; inci += ai_; }
    }
    const float exs = incs - ps, exi = inci - pi;

    // transposed writes: [idx][dd]
    if (lane == 0)
        g_tab_t[tbase + 0 * 32 + dd] = make_float2(bs, bi);
    g_tab_t[tbase + (2 * lane + 1) * 32 + dd] =
        make_float2(bs + exs + v0s, bi + exi + v0i);
    g_tab_t[tbase + (2 * lane + 2) * 32 + dd] =
        make_float2(bs + incs, bi + inci);
    g_knot_t[kbase + (2 * lane) * 32 + dd]     = s_kt[w][2 * lane];
    g_knot_t[kbase + (2 * lane + 1) * 32 + dd] = s_kt[w][2 * lane + 1];

    PDL_TRIGGER();
}

// =====================================================================
// Kernel 2: eval u — transposed tables (R14) + PDL prologue overlap:
// batch-1 x prefetched into registers BEFORE griddepcontrol.wait.
// grid = (64 rowchunks x 8 dgroups) = 512 CTAs, 512 threads, 4 CTA/SM.
// =====================================================================
__global__ __launch_bounds__(512)
void eval_u_kernel(const float* __restrict__ x)
{
    __shared__ float  skt[64 * 32];    // knots  [j][dd]
    __shared__ float2 stab[65 * 32];   // (slope,inter) [k][dd]

    const int tid = threadIdx.x;
    const int dgr = blockIdx.y;
    const int d0  = dgr * 32;

    const int dd  = tid & 31;
    const int bl  = tid >> 5;
    const int d   = d0 + dd;
    const int rowbase = blockIdx.x * 256;

    // ---- independent prologue: prefetch batch-1 x (8 LDG in flight) ----
    float xv0[8];
    #pragma unroll
    for (int j = 0; j < 8; j++)
        xv0[j] = __ldg(&x[(size_t)(rowbase + bl + j * 16) * D_FEAT + d]);

    // ---- wait for prep's tables ----
    PDL_WAIT();

    // coalesced fills
    #pragma unroll
    for (int i = tid; i < 64 * 32; i += 512)
        skt[i] = g_knot_t[dgr * 64 * 32 + i];
    for (int i = tid; i < 65 * 32; i += 512)
        stab[i] = g_tab_t[dgr * 65 * 32 + i];
    __syncthreads();

    // level-1 pivots in registers: knot[8g+7]
    float pv[8];
    #pragma unroll
    for (int g = 0; g < 8; g++) pv[g] = skt[(g * 8 + 7) * 32 + dd];

    // ---- batch 1 (prefetched x) ----
    {
        int lo[8];
        #pragma unroll
        for (int j = 0; j < 8; j++) {
            const float xj = xv0[j];
            int g = 0;
            #pragma unroll
            for (int gg = 0; gg < 8; gg++) g += (pv[gg] < xj);
            const int gm = ((g < 8) ? g : 7) << 3;
            int l2 = (skt[(gm + 3) * 32 + dd] < xj) ? 4 : 0;
            l2 += (skt[(gm + l2 + 1) * 32 + dd] < xj) ? 2 : 0;
            l2 += (skt[(gm + l2) * 32 + dd] < xj) ? 1 : 0;
            lo[j] = (g < 8) ? (gm + l2) : 64;
        }
        #pragma unroll
        for (int j = 0; j < 8; j++) {
            const float2 si = stab[lo[j] * 32 + dd];
            float u = fmaf(si.x, xv0[j], si.y);
            g_u[(size_t)(rowbase + bl + j * 16) * D_FEAT + d] = __float2half(u);
        }
    }
    // ---- batch 2 ----
    {
        const int rb = rowbase + 128 + bl;
        float xv[8];
        #pragma unroll
        for (int j = 0; j < 8; j++)
            xv[j] = __ldg(&x[(size_t)(rb + j * 16) * D_FEAT + d]);

        int lo[8];
        #pragma unroll
        for (int j = 0; j < 8; j++) {
            const float xj = xv[j];
            int g = 0;
            #pragma unroll
            for (int gg = 0; gg < 8; gg++) g += (pv[gg] < xj);
            const int gm = ((g < 8) ? g : 7) << 3;
            int l2 = (skt[(gm + 3) * 32 + dd] < xj) ? 4 : 0;
            l2 += (skt[(gm + l2 + 1) * 32 + dd] < xj) ? 2 : 0;
            l2 += (skt[(gm + l2) * 32 + dd] < xj) ? 1 : 0;
            lo[j] = (g < 8) ? (gm + l2) : 64;
        }
        #pragma unroll
        for (int j = 0; j < 8; j++) {
            const float2 si = stab[lo[j] * 32 + dd];
            float u = fmaf(si.x, xv[j], si.y);
            g_u[(size_t)(rb + j * 16) * D_FEAT + d] = __float2half(u);
        }
    }

    PDL_TRIGGER();
}

// =====================================================================
// Kernel 3: GEMM out = u @ Wc^T + bc, M=128 x N=256 x K=256 (R11 body)
// + PDL prologue: ALL B (Wc) cp.asyncs issued before griddepcontrol.wait
// (g_wc written by prep, which fully completed before eval's trigger).
// Groups: g0 = all B, g1..g4 = A chunks; chunk c waits group(3-c).
// =====================================================================
#define CH      64
#define CH_PAD  72
#define A_ST_H  (128 * CH_PAD)
#define B_ST_H  (256 * CH_PAD)
#define N_STAGE 4
#define GEMM_SMEM_BYTES ((A_ST_H + B_ST_H) * 2 * N_STAGE)   // 221184
#define GTHREADS 256

__device__ __forceinline__ void cp16(uint32_t dst, const void* src) {
    asm volatile("cp.async.cg.shared.global [%0], [%1], 16;"
                 :: "r"(dst), "l"(src));
}
#define CP_COMMIT() asm volatile("cp.async.commit_group;" ::: "memory")
#define CP_WAIT(n)  asm volatile("cp.async.wait_group %0;" :: "n"(n) : "memory")

__device__ __forceinline__ void ldsm_x4(uint32_t* r, uint32_t addr) {
    asm volatile("ldmatrix.sync.aligned.m8n8.x4.shared.b16 {%0,%1,%2,%3}, [%4];"
                 : "=r"(r[0]), "=r"(r[1]), "=r"(r[2]), "=r"(r[3]) : "r"(addr));
}
__device__ __forceinline__ void mma_16816(float* c, const uint32_t* a,
                                          const uint32_t* b) {
    asm volatile(
        "mma.sync.aligned.m16n8k16.row.col.f32.f16.f16.f32 "
        "{%0,%1,%2,%3}, {%4,%5,%6,%7}, {%8,%9}, {%0,%1,%2,%3};"
        : "+f"(c[0]), "+f"(c[1]), "+f"(c[2]), "+f"(c[3])
        : "r"(a[0]), "r"(a[1]), "r"(a[2]), "r"(a[3]), "r"(b[0]), "r"(b[1]));
}

__global__ __launch_bounds__(GTHREADS, 1)
void gemm_kernel(const float* __restrict__ bc, float* __restrict__ out)
{
    extern __shared__ __half smem[];
    __half* As = smem;
    __half* Bs = smem + N_STAGE * A_ST_H;

    const int tid = threadIdx.x;
    const int wid = tid >> 5;
    const int lid = tid & 31;
    const int m0  = blockIdx.x * 128;

    const uint32_t as_u32 = smem_u32(As);
    const uint32_t bs_u32 = smem_u32(Bs);
    const __half* Asrc = g_u + (size_t)m0 * D_FEAT;

    // ---- independent prologue: ALL B chunks (g_wc from prep) ----
    #pragma unroll
    for (int c = 0; c < 4; c++) {
        #pragma unroll
        for (int i = 0; i < 8; i++) {
            int idx = tid + i * GTHREADS;
            int row = idx >> 3, k8 = idx & 7;
            cp16(bs_u32 + (uint32_t)((c * B_ST_H + row * CH_PAD + k8 * 8) * 2),
                 g_wc + row * D_FEAT + c * CH + k8 * 8);
        }
    }
    CP_COMMIT();                   // group0 = all B

    // ---- wait for eval's u ----
    PDL_WAIT();

    // ---- A chunks, one commit group each (groups 1..4) ----
    #pragma unroll
    for (int c = 0; c < 4; c++) {
        #pragma unroll
        for (int i = 0; i < 4; i++) {
            int idx = tid + i * GTHREADS;
            int row = idx >> 3, k8 = idx & 7;
            cp16(as_u32 + (uint32_t)((c * A_ST_H + row * CH_PAD + k8 * 8) * 2),
                 Asrc + row * D_FEAT + c * CH + k8 * 8);
        }
        CP_COMMIT();
    }

    const int warp_m = wid >> 2;   // 0..1
    const int warp_n = wid & 3;    // 0..3

    const int a_row = warp_m * 64 + (lid & 15);
    const uint32_t a_lane = as_u32
        + (uint32_t)((a_row * CH_PAD + ((lid >> 4) << 3)) * 2);
    const int b_row = warp_n * 64 + (((lid >> 4) & 1) << 3) + (lid & 7);
    const uint32_t b_lane = bs_u32
        + (uint32_t)((b_row * CH_PAD + (((lid >> 3) & 1) << 3)) * 2);

    float acc[4][8][4];
    #pragma unroll
    for (int i = 0; i < 4; i++)
        #pragma unroll
        for (int j = 0; j < 8; j++)
            #pragma unroll
            for (int q = 0; q < 4; q++) acc[i][j][q] = 0.0f;

    #pragma unroll
    for (int c = 0; c < 4; c++) {
        // need group0 (B) + groups 1..c+1 (A chunks 0..c) done
        if      (c == 0) { CP_WAIT(3); }
        else if (c == 1) { CP_WAIT(2); }
        else if (c == 2) { CP_WAIT(1); }
        else             { CP_WAIT(0); }
        __syncthreads();

        const uint32_t a_st = a_lane + (uint32_t)(c * A_ST_H * 2);
        const uint32_t b_st = b_lane + (uint32_t)(c * B_ST_H * 2);

        #pragma unroll
        for (int ks = 0; ks < 4; ks++) {
            const uint32_t kb = (uint32_t)(ks * 32);
            uint32_t afr[4][4];
            #pragma unroll
            for (int tm = 0; tm < 4; tm++)
                ldsm_x4(afr[tm], a_st + (uint32_t)(tm * 16 * CH_PAD * 2) + kb);
            uint32_t bfr[8][2];
            #pragma unroll
            for (int pn = 0; pn < 4; pn++) {
                uint32_t q[4];
                ldsm_x4(q, b_st + (uint32_t)(pn * 16 * CH_PAD * 2) + kb);
                bfr[2 * pn][0]     = q[0];
                bfr[2 * pn][1]     = q[1];
                bfr[2 * pn + 1][0] = q[2];
                bfr[2 * pn + 1][1] = q[3];
            }
            #pragma unroll
            for (int tm = 0; tm < 4; tm++)
                #pragma unroll
                for (int tn = 0; tn < 8; tn++)
                    mma_16816(acc[tm][tn], afr[tm], bfr[tn]);
        }
    }

    const int qr = lid >> 2;
    const int qc = (lid & 3) * 2;
    #pragma unroll
    for (int tn = 0; tn < 8; tn++) {
        const int cb = warp_n * 64 + tn * 8 + qc;
        const float2 bcv = *reinterpret_cast<const float2*>(bc + cb);
        #pragma unroll
        for (int tm = 0; tm < 4; tm++) {
            const int r = m0 + warp_m * 64 + tm * 16 + qr;
            float2 v0, v1;
            v0.x = acc[tm][tn][0] + bcv.x;
            v0.y = acc[tm][tn][1] + bcv.y;
            v1.x = acc[tm][tn][2] + bcv.x;
            v1.y = acc[tm][tn][3] + bcv.y;
            *reinterpret_cast<float2*>(out + (size_t)r * O_OUT + cb) = v0;
            *reinterpret_cast<float2*>(out + (size_t)(r + 8) * O_OUT + cb) = v1;
        }
    }
}

// =====================================================================
// launch — eval & gemm launched with ProgrammaticStreamSerialization
// =====================================================================
extern "C" void kernel_launch(void* const* d_in, const int* in_sizes, int n_in,
                              void* d_out, int out_size)
{
    const float* x  = (const float*)d_in[0];
    const float* W1 = (const float*)d_in[1];
    const float* b1 = (const float*)d_in[2];
    const float* W2 = (const float*)d_in[3];
    const float* b2 = (const float*)d_in[4];
    const float* Wc = (const float*)d_in[5];
    const float* bc = (const float*)d_in[6];
    float* out = (float*)d_out;

    prep_kernel<<<192, 128>>>(W1, b1, W2, b2, Wc);

    cudaLaunchAttribute pdl[1];
    pdl[0].id = cudaLaunchAttributeProgrammaticStreamSerialization;
    pdl[0].val.programmaticStreamSerializationAllowed = 1;

    {
        cudaLaunchConfig_t cfg = {};
        cfg.gridDim  = dim3(B_ROWS / 256, D_FEAT / 32, 1);
        cfg.blockDim = dim3(512, 1, 1);
        cfg.dynamicSmemBytes = 0;
        cfg.stream = 0;
        cfg.attrs = pdl;
        cfg.numAttrs = 1;
        cudaLaunchKernelEx(&cfg, eval_u_kernel, x);
    }
    {
        cudaLaunchConfig_t cfg = {};
        cfg.gridDim  = dim3(B_ROWS / 128, 1, 1);
        cfg.blockDim = dim3(GTHREADS, 1, 1);
        cfg.dynamicSmemBytes = GEMM_SMEM_BYTES;
        cfg.stream = 0;
        cfg.attrs = pdl;
        cfg.numAttrs = 1;
        cudaLaunchKernelEx(&cfg, gemm_kernel, bc, out);
    }
}

namespace {
struct AttrInit {
    AttrInit() {
        cudaFuncSetAttribute(gemm_kernel,
                             cudaFuncAttributeMaxDynamicSharedMemorySize,
                             GEMM_SMEM_BYTES);
    }
} g_attr_init;
}

// round 16
// speedup vs baseline: 1.0767x; 1.0767x over previous
#include <cuda_runtime.h>
#include <cuda_fp16.h>
#include <cstdint>

// ---------------- problem constants ----------------
#define B_ROWS 16384
#define D_FEAT 256
#define H_HID  64
#define O_OUT  256

// ---------------- device scratch (static, allocation-free) ----------------
__device__ __half  g_u[(size_t)B_ROWS * D_FEAT];     // 8.4 MB fp16 u
__device__ __half  g_wc[(size_t)O_OUT * D_FEAT];     // Wc fp16
// transposed tables: [dgroup][idx][dd]  (dd = d & 31, dgroup = d >> 5)
__device__ float   g_knot_t[8 * 64 * 32];
__device__ float2  g_tab_t[8 * 65 * 32];             // (slope, intercept)

__device__ __forceinline__ uint32_t smem_u32(const void* p) {
    uint32_t a;
    asm("{ .reg .u64 t; cvta.to.shared.u64 t, %1; cvt.u32.u64 %0, t; }"
        : "=r"(a) : "l"(p));
    return a;
}

// PDL primitives (sm_90 baseline PTX — survives the compute_103 stage)
#define PDL_WAIT()    asm volatile("griddepcontrol.wait;" ::: "memory")
#define PDL_TRIGGER() asm volatile("griddepcontrol.launch_dependents;" ::: "memory")

// =====================================================================
// Kernel 1: PWL table build (blocks 0..63, transposed output layout)
//           + Wc fp16 convert (blocks 64..191). Triggers eval via PDL.
// =====================================================================
__global__ __launch_bounds__(128)
void prep_kernel(const float* __restrict__ W1,
                 const float* __restrict__ b1,
                 const float* __restrict__ W2,
                 const float* __restrict__ b2,
                 const float* __restrict__ Wc)
{
    const int bid = blockIdx.x;

    if (bid >= 64) {
        const float4* W4 = reinterpret_cast<const float4*>(Wc);
        int idx = (bid - 64) * 128 + threadIdx.x;
        float4 f = W4[idx];
        __half2 h0 = __float22half2_rn(make_float2(f.x, f.y));
        __half2 h1 = __float22half2_rn(make_float2(f.z, f.w));
        uint2 pk;
        pk.x = *reinterpret_cast<uint32_t*>(&h0);
        pk.y = *reinterpret_cast<uint32_t*>(&h1);
        *reinterpret_cast<uint2*>(&g_wc[idx * 4]) = pk;
        PDL_TRIGGER();
        return;
    }

    const int w    = threadIdx.x >> 5;
    const int lane = threadIdx.x & 31;
    const int d    = bid * 4 + w;
    const int dg   = d >> 5;            // dgroup 0..7
    const int dd   = d & 31;
    const int kbase = dg * 64 * 32;
    const int tbase = dg * 65 * 32;

    __shared__ float s_t[4][64], s_ds[4][64], s_di[4][64];
    __shared__ float s_kt[4][64], s_kds[4][64], s_kdi[4][64];

    float t[2], ds[2], di[2];
    float bs = 0.0f, bi = 0.0f;
    #pragma unroll
    for (int i = 0; i < 2; i++) {
        const int h  = lane + i * 32;
        const float w1 = W1[d * H_HID + h];
        const float bb = b1[d * H_HID + h];
        const float w2 = W2[d * H_HID + h];
        if (w1 != 0.0f) {
            t[i]  = -bb / w1;
            ds[i] = fabsf(w1) * w2;
            di[i] = (w1 > 0.0f) ? (w2 * bb) : (-w2 * bb);
            if (w1 < 0.0f) { bs += w1 * w2; bi += w2 * bb; }
        } else {
            t[i]  = __int_as_float(0x7f800000);
            ds[i] = 0.0f;
            di[i] = 0.0f;
            bi   += w2 * fmaxf(bb, 0.0f);
        }
        s_t[w][h]  = t[i];
        s_ds[w][h] = ds[i];
        s_di[w][h] = di[i];
    }
    #pragma unroll
    for (int off = 16; off >= 1; off >>= 1) {
        bs += __shfl_xor_sync(0xffffffffu, bs, off);
        bi += __shfl_xor_sync(0xffffffffu, bi, off);
    }
    bi += b2[d];

    __syncwarp();
    int r0 = 0, r1 = 0;
    const float t0 = t[0], t1 = t[1];
    #pragma unroll 16
    for (int j = 0; j < 64; j++) {
        float tj = s_t[w][j];
        r0 += (tj < t0) || (tj == t0 && j < lane);
        r1 += (tj < t1) || (tj == t1 && j < lane + 32);
    }
    s_kt[w][r0]  = t0;  s_kds[w][r0] = ds[0]; s_kdi[w][r0] = di[0];
    s_kt[w][r1]  = t1;  s_kds[w][r1] = ds[1]; s_kdi[w][r1] = di[1];
    __syncwarp();

    const float v0s = s_kds[w][2 * lane],     v1s = s_kds[w][2 * lane + 1];
    const float v0i = s_kdi[w][2 * lane],     v1i = s_kdi[w][2 * lane + 1];
    float incs = v0s + v1s, inci = v0i + v1i;
    const float ps = incs, pi = inci;
    #pragma unroll
    for (int off = 1; off < 32; off <<= 1) {
        float as_ = __shfl_up_sync(0xffffffffu, incs, off);
        float ai_ = __shfl_up_sync(0xffffffffu, inci, off);
        if (lane >= off) { incs += as_; inci += ai_; }
    }
    const float exs = incs - ps, exi = inci - pi;

    if (lane == 0)
        g_tab_t[tbase + 0 * 32 + dd] = make_float2(bs, bi);
    g_tab_t[tbase + (2 * lane + 1) * 32 + dd] =
        make_float2(bs + exs + v0s, bi + exi + v0i);
    g_tab_t[tbase + (2 * lane + 2) * 32 + dd] =
        make_float2(bs + incs, bi + inci);
    g_knot_t[kbase + (2 * lane) * 32 + dd]     = s_kt[w][2 * lane];
    g_knot_t[kbase + (2 * lane + 1) * 32 + dd] = s_kt[w][2 * lane + 1];

    PDL_TRIGGER();
}

// =====================================================================
// Kernel 2: eval u — transposed tables (R14) + prep->eval PDL only:
// batch-1 x prefetched into registers BEFORE griddepcontrol.wait.
// grid = (64 rowchunks x 8 dgroups) = 512 CTAs, 512 threads, 4 CTA/SM.
// =====================================================================
__global__ __launch_bounds__(512)
void eval_u_kernel(const float* __restrict__ x)
{
    __shared__ float  skt[64 * 32];    // knots  [j][dd]
    __shared__ float2 stab[65 * 32];   // (slope,inter) [k][dd]

    const int tid = threadIdx.x;
    const int dgr = blockIdx.y;
    const int d0  = dgr * 32;

    const int dd  = tid & 31;
    const int bl  = tid >> 5;
    const int d   = d0 + dd;
    const int rowbase = blockIdx.x * 256;

    // independent prologue: prefetch batch-1 x (8 LDG in flight)
    float xv0[8];
    #pragma unroll
    for (int j = 0; j < 8; j++)
        xv0[j] = __ldg(&x[(size_t)(rowbase + bl + j * 16) * D_FEAT + d]);

    // wait for prep's tables + g_wc
    PDL_WAIT();

    // coalesced fills
    #pragma unroll
    for (int i = tid; i < 64 * 32; i += 512)
        skt[i] = g_knot_t[dgr * 64 * 32 + i];
    for (int i = tid; i < 65 * 32; i += 512)
        stab[i] = g_tab_t[dgr * 65 * 32 + i];
    __syncthreads();

    // level-1 pivots in registers: knot[8g+7]
    float pv[8];
    #pragma unroll
    for (int g = 0; g < 8; g++) pv[g] = skt[(g * 8 + 7) * 32 + dd];

    // batch 1 (prefetched x)
    {
        int lo[8];
        #pragma unroll
        for (int j = 0; j < 8; j++) {
            const float xj = xv0[j];
            int g = 0;
            #pragma unroll
            for (int gg = 0; gg < 8; gg++) g += (pv[gg] < xj);
            const int gm = ((g < 8) ? g : 7) << 3;
            int l2 = (skt[(gm + 3) * 32 + dd] < xj) ? 4 : 0;
            l2 += (skt[(gm + l2 + 1) * 32 + dd] < xj) ? 2 : 0;
            l2 += (skt[(gm + l2) * 32 + dd] < xj) ? 1 : 0;
            lo[j] = (g < 8) ? (gm + l2) : 64;
        }
        #pragma unroll
        for (int j = 0; j < 8; j++) {
            const float2 si = stab[lo[j] * 32 + dd];
            float u = fmaf(si.x, xv0[j], si.y);
            g_u[(size_t)(rowbase + bl + j * 16) * D_FEAT + d] = __float2half(u);
        }
    }
    // batch 2
    {
        const int rb = rowbase + 128 + bl;
        float xv[8];
        #pragma unroll
        for (int j = 0; j < 8; j++)
            xv[j] = __ldg(&x[(size_t)(rb + j * 16) * D_FEAT + d]);

        int lo[8];
        #pragma unroll
        for (int j = 0; j < 8; j++) {
            const float xj = xv[j];
            int g = 0;
            #pragma unroll
            for (int gg = 0; gg < 8; gg++) g += (pv[gg] < xj);
            const int gm = ((g < 8) ? g : 7) << 3;
            int l2 = (skt[(gm + 3) * 32 + dd] < xj) ? 4 : 0;
            l2 += (skt[(gm + l2 + 1) * 32 + dd] < xj) ? 2 : 0;
            l2 += (skt[(gm + l2) * 32 + dd] < xj) ? 1 : 0;
            lo[j] = (g < 8) ? (gm + l2) : 64;
        }
        #pragma unroll
        for (int j = 0; j < 8; j++) {
            const float2 si = stab[lo[j] * 32 + dd];
            float u = fmaf(si.x, xv[j], si.y);
            g_u[(size_t)(rb + j * 16) * D_FEAT + d] = __float2half(u);
        }
    }
}

// =====================================================================
// Kernel 3: GEMM out = u @ Wc^T + bc, M=128 x N=256 x K=256 (R14 —
// plain serialized launch; NO PDL: early GEMM CTAs squat smem and
// block eval waves, measured -2us in R15).
// 256 threads = 8 warps (2m x 4n), warp tile 64x64, 4-stage prefetch.
// =====================================================================
#define CH      64
#define CH_PAD  72
#define A_ST_H  (128 * CH_PAD)
#define B_ST_H  (256 * CH_PAD)
#define N_STAGE 4
#define GEMM_SMEM_BYTES ((A_ST_H + B_ST_H) * 2 * N_STAGE)   // 221184
#define GTHREADS 256

__device__ __forceinline__ void cp16(uint32_t dst, const void* src) {
    asm volatile("cp.async.cg.shared.global [%0], [%1], 16;"
                 :: "r"(dst), "l"(src));
}
#define CP_COMMIT() asm volatile("cp.async.commit_group;" ::: "memory")
#define CP_WAIT(n)  asm volatile("cp.async.wait_group %0;" :: "n"(n) : "memory")

__device__ __forceinline__ void ldsm_x4(uint32_t* r, uint32_t addr) {
    asm volatile("ldmatrix.sync.aligned.m8n8.x4.shared.b16 {%0,%1,%2,%3}, [%4];"
                 : "=r"(r[0]), "=r"(r[1]), "=r"(r[2]), "=r"(r[3]) : "r"(addr));
}
__device__ __forceinline__ void mma_16816(float* c, const uint32_t* a,
                                          const uint32_t* b) {
    asm volatile(
        "mma.sync.aligned.m16n8k16.row.col.f32.f16.f16.f32 "
        "{%0,%1,%2,%3}, {%4,%5,%6,%7}, {%8,%9}, {%0,%1,%2,%3};"
        : "+f"(c[0]), "+f"(c[1]), "+f"(c[2]), "+f"(c[3])
        : "r"(a[0]), "r"(a[1]), "r"(a[2]), "r"(a[3]), "r"(b[0]), "r"(b[1]));
}

struct GemmCtx {
    uint32_t as_u32, bs_u32;
    const __half* Asrc;
    int tid;
};

__device__ __forceinline__ void issue_chunk(const GemmCtx& g, int c, int st) {
    #pragma unroll
    for (int i = 0; i < 4; i++) {
        int idx = g.tid + i * GTHREADS;
        int row = idx >> 3, k8 = idx & 7;
        cp16(g.as_u32 + (uint32_t)((st * A_ST_H + row * CH_PAD + k8 * 8) * 2),
             g.Asrc + row * D_FEAT + c * CH + k8 * 8);
    }
    #pragma unroll
    for (int i = 0; i < 8; i++) {
        int idx = g.tid + i * GTHREADS;
        int row = idx >> 3, k8 = idx & 7;
        cp16(g.bs_u32 + (uint32_t)((st * B_ST_H + row * CH_PAD + k8 * 8) * 2),
             g_wc + row * D_FEAT + c * CH + k8 * 8);
    }
}

__global__ __launch_bounds__(GTHREADS, 1)
void gemm_kernel(const float* __restrict__ bc, float* __restrict__ out)
{
    extern __shared__ __half smem[];
    __half* As = smem;
    __half* Bs = smem + N_STAGE * A_ST_H;

    const int tid = threadIdx.x;
    const int wid = tid >> 5;
    const int lid = tid & 31;
    const int m0  = blockIdx.x * 128;

    GemmCtx g;
    g.as_u32 = smem_u32(As);
    g.bs_u32 = smem_u32(Bs);
    g.Asrc   = g_u + (size_t)m0 * D_FEAT;
    g.tid    = tid;

    issue_chunk(g, 0, 0); CP_COMMIT();
    issue_chunk(g, 1, 1); CP_COMMIT();
    issue_chunk(g, 2, 2); CP_COMMIT();
    issue_chunk(g, 3, 3); CP_COMMIT();

    const int warp_m = wid >> 2;   // 0..1
    const int warp_n = wid & 3;    // 0..3

    const int a_row = warp_m * 64 + (lid & 15);
    const uint32_t a_lane = g.as_u32
        + (uint32_t)((a_row * CH_PAD + ((lid >> 4) << 3)) * 2);
    const int b_row = warp_n * 64 + (((lid >> 4) & 1) << 3) + (lid & 7);
    const uint32_t b_lane = g.bs_u32
        + (uint32_t)((b_row * CH_PAD + (((lid >> 3) & 1) << 3)) * 2);

    float acc[4][8][4];
    #pragma unroll
    for (int i = 0; i < 4; i++)
        #pragma unroll
        for (int j = 0; j < 8; j++)
            #pragma unroll
            for (int q = 0; q < 4; q++) acc[i][j][q] = 0.0f;

    #pragma unroll
    for (int c = 0; c < 4; c++) {
        if      (c == 0) { CP_WAIT(3); }
        else if (c == 1) { CP_WAIT(2); }
        else if (c == 2) { CP_WAIT(1); }
        else             { CP_WAIT(0); }
        __syncthreads();

        const uint32_t a_st = a_lane + (uint32_t)(c * A_ST_H * 2);
        const uint32_t b_st = b_lane + (uint32_t)(c * B_ST_H * 2);

        #pragma unroll
        for (int ks = 0; ks < 4; ks++) {
            const uint32_t kb = (uint32_t)(ks * 32);
            uint32_t afr[4][4];
            #pragma unroll
            for (int tm = 0; tm < 4; tm++)
                ldsm_x4(afr[tm], a_st + (uint32_t)(tm * 16 * CH_PAD * 2) + kb);
            uint32_t bfr[8][2];
            #pragma unroll
            for (int pn = 0; pn < 4; pn++) {
                uint32_t q[4];
                ldsm_x4(q, b_st + (uint32_t)(pn * 16 * CH_PAD * 2) + kb);
                bfr[2 * pn][0]     = q[0];
                bfr[2 * pn][1]     = q[1];
                bfr[2 * pn + 1][0] = q[2];
                bfr[2 * pn + 1][1] = q[3];
            }
            #pragma unroll
            for (int tm = 0; tm < 4; tm++)
                #pragma unroll
                for (int tn = 0; tn < 8; tn++)
                    mma_16816(acc[tm][tn], afr[tm], bfr[tn]);
        }
    }

    const int qr = lid >> 2;
    const int qc = (lid & 3) * 2;
    #pragma unroll
    for (int tn = 0; tn < 8; tn++) {
        const int cb = warp_n * 64 + tn * 8 + qc;
        const float2 bcv = *reinterpret_cast<const float2*>(bc + cb);
        #pragma unroll
        for (int tm = 0; tm < 4; tm++) {
            const int r = m0 + warp_m * 64 + tm * 16 + qr;
            float2 v0, v1;
            v0.x = acc[tm][tn][0] + bcv.x;
            v0.y = acc[tm][tn][1] + bcv.y;
            v1.x = acc[tm][tn][2] + bcv.x;
            v1.y = acc[tm][tn][3] + bcv.y;
            *reinterpret_cast<float2*>(out + (size_t)r * O_OUT + cb) = v0;
            *reinterpret_cast<float2*>(out + (size_t)(r + 8) * O_OUT + cb) = v1;
        }
    }
}

// =====================================================================
// launch — PDL only on prep->eval; gemm fully serialized.
// =====================================================================
extern "C" void kernel_launch(void* const* d_in, const int* in_sizes, int n_in,
                              void* d_out, int out_size)
{
    const float* x  = (const float*)d_in[0];
    const float* W1 = (const float*)d_in[1];
    const float* b1 = (const float*)d_in[2];
    const float* W2 = (const float*)d_in[3];
    const float* b2 = (const float*)d_in[4];
    const float* Wc = (const float*)d_in[5];
    const float* bc = (const float*)d_in[6];
    float* out = (float*)d_out;

    prep_kernel<<<192, 128>>>(W1, b1, W2, b2, Wc);

    cudaLaunchAttribute pdl[1];
    pdl[0].id = cudaLaunchAttributeProgrammaticStreamSerialization;
    pdl[0].val.programmaticStreamSerializationAllowed = 1;
    {
        cudaLaunchConfig_t cfg = {};
        cfg.gridDim  = dim3(B_ROWS / 256, D_FEAT / 32, 1);
        cfg.blockDim = dim3(512, 1, 1);
        cfg.dynamicSmemBytes = 0;
        cfg.stream = 0;
        cfg.attrs = pdl;
        cfg.numAttrs = 1;
        cudaLaunchKernelEx(&cfg, eval_u_kernel, x);
    }

    gemm_kernel<<<B_ROWS / 128, GTHREADS, GEMM_SMEM_BYTES>>>(bc, out);
}

namespace {
struct AttrInit {
    AttrInit() {
        cudaFuncSetAttribute(gemm_kernel,
                             cudaFuncAttributeMaxDynamicSharedMemorySize,
                             GEMM_SMEM_BYTES);
    }
} g_attr_init;
}